// round 8
// baseline (speedup 1.0000x reference)
#include <cuda_runtime.h>
#include <cuda_fp16.h>
#include <cstdint>

#define TT 1024
#define HH 50
#define PP 16
#define RH 72   // ring row stride in halfs (144B -> 4-way flush conflicts only)

__device__ __forceinline__ float tanh_hw(float v) {
    float r; asm("tanh.approx.f32 %0, %1;" : "=f"(r) : "f"(v)); return r;
}
__device__ __forceinline__ __half2 as_h2(unsigned u) {
    return *reinterpret_cast<const __half2*>(&u);
}

__global__ __launch_bounds__(64, 7)
void lstm_fused_kernel(const float* __restrict__ x,
                       const float* __restrict__ params,
                       const float* __restrict__ W_ih,
                       const float* __restrict__ W_hh,
                       const float* __restrict__ b_ih,
                       const float* __restrict__ b_hh,
                       const float* __restrict__ W_lin,
                       const float* __restrict__ b_lin,
                       float* __restrict__ out)
{
    __shared__ __align__(16) float  xs[TT];         // this batch's input row
    __shared__ __align__(16) __half ring[32][RH];   // fp16 h ring (one batch)
    __shared__ __align__(16) float  wlin[68];

    const int tid = threadIdx.x;                    // 0..63, unit index
    const int b   = blockIdx.x;                     // batch
    const int jj  = min(tid, HH - 1);

    // ---- init: stage x row, wlin, zero h[-1] ----
    {
        const float4* xr = reinterpret_cast<const float4*>(x + (size_t)b * TT);
        #pragma unroll
        for (int i = 0; i < 4; ++i)
            reinterpret_cast<float4*>(xs)[tid + 64 * i] = xr[tid + 64 * i];
        if (tid < 50) ring[31][tid] = __float2half_rn(0.0f);
        wlin[tid] = (tid < HH + PP) ? W_lin[tid] : 0.0f;
        if (tid < 4) wlin[64 + tid] = (64 + tid < HH + PP) ? W_lin[64 + tid] : 0.0f;
    }
    const float blin = b_lin[0];

    // ---- per-thread: all 4 gate rows (i,f,g,o) for unit jj ----
    __half2 w[4][25];
    float wih[4], bias[4];
    #pragma unroll
    for (int k = 0; k < 4; ++k) {
        const int r = k * HH + jj;
        wih[k]  = W_ih[r];
        bias[k] = b_ih[r] + b_hh[r];
        const float2* wr = reinterpret_cast<const float2*>(W_hh + r * HH);
        #pragma unroll
        for (int q = 0; q < 25; ++q) { float2 v = wr[q]; w[k][q] = __floats2half2_rn(v.x, v.y); }
    }
    __syncthreads();

    float c = 0.0f;

    #pragma unroll 1
    for (int t = 0; t < TT; ++t) {
        const int cur  = t & 31;
        const int prev = (t + 31) & 31;

        // h[t-1]: 6 LDS.128 + 1 LDS.32, full-broadcast
        uint4 hv[6];
        const uint4* rp = reinterpret_cast<const uint4*>(&ring[prev][0]);
        #pragma unroll
        for (int q = 0; q < 6; ++q) hv[q] = rp[q];
        // tail pair h48,h49 = 32-bit word index 24 (words 0..23 are halfs 0..47)
        const unsigned htail = reinterpret_cast<const unsigned*>(&ring[prev][0])[24];
        const float xv = xs[t];

        float raw[4];
        #pragma unroll
        for (int k = 0; k < 4; ++k) {
            __half2 a0 = __floats2half2_rn(0.f, 0.f), a1 = a0;
            #pragma unroll
            for (int q = 0; q < 6; ++q) {
                a0 = __hfma2(w[k][4 * q + 0], as_h2(hv[q].x), a0);
                a1 = __hfma2(w[k][4 * q + 1], as_h2(hv[q].y), a1);
                a0 = __hfma2(w[k][4 * q + 2], as_h2(hv[q].z), a0);
                a1 = __hfma2(w[k][4 * q + 3], as_h2(hv[q].w), a1);
            }
            a0 = __hfma2(w[k][24], as_h2(htail), a0);
            const __half2 s = __hadd2(a0, a1);
            raw[k] = fmaf(xv, wih[k], bias[k]) + __low2float(s) + __high2float(s);
        }

        const float vi = fmaf(0.5f, tanh_hw(0.5f * raw[0]), 0.5f);
        const float vf = fmaf(0.5f, tanh_hw(0.5f * raw[1]), 0.5f);
        const float vg = tanh_hw(raw[2]);
        const float vo = fmaf(0.5f, tanh_hw(0.5f * raw[3]), 0.5f);

        c = fmaf(vf, c, vi * vg);
        const float h = vo * tanh_hw(c);
        if (tid < HH) ring[cur][tid] = __float2half_rn(h);

        __syncthreads();                            // h[cur] visible to both warps

        // ---- bulk output flush every 32 steps: warp 0, 1 thread per timestep ----
        if ((t & 31) == 31) {
            if (tid < 32) {
                const int tg = t - 31 + tid;
                const __half* hr = ring[tid];
                float s = blin;
                #pragma unroll
                for (int q = 0; q < 6; ++q) {
                    uint4 v = reinterpret_cast<const uint4*>(hr)[q];   // 4-way conflict max
                    float2 f0 = __half22float2(as_h2(v.x));
                    float2 f1 = __half22float2(as_h2(v.y));
                    float2 f2 = __half22float2(as_h2(v.z));
                    float2 f3 = __half22float2(as_h2(v.w));
                    s = fmaf(f0.x, wlin[8 * q + 0], s); s = fmaf(f0.y, wlin[8 * q + 1], s);
                    s = fmaf(f1.x, wlin[8 * q + 2], s); s = fmaf(f1.y, wlin[8 * q + 3], s);
                    s = fmaf(f2.x, wlin[8 * q + 4], s); s = fmaf(f2.y, wlin[8 * q + 5], s);
                    s = fmaf(f3.x, wlin[8 * q + 6], s); s = fmaf(f3.y, wlin[8 * q + 7], s);
                }
                {
                    // tail pair h48,h49 = word index 24
                    float2 ft = __half22float2(as_h2(reinterpret_cast<const unsigned*>(hr)[24]));
                    s = fmaf(ft.x, wlin[48], s); s = fmaf(ft.y, wlin[49], s);
                }
                const float4* p4 = reinterpret_cast<const float4*>(
                    params + ((size_t)b * TT + tg) * PP);
                #pragma unroll
                for (int q = 0; q < 4; ++q) {
                    float4 p = __ldg(p4 + q);
                    s = fmaf(p.x, wlin[HH + 4 * q + 0], s);
                    s = fmaf(p.y, wlin[HH + 4 * q + 1], s);
                    s = fmaf(p.z, wlin[HH + 4 * q + 2], s);
                    s = fmaf(p.w, wlin[HH + 4 * q + 3], s);
                }
                out[(size_t)b * TT + tg] = s;
            }
            __syncthreads();                        // flush reads done before slot reuse
        }
    }
}

extern "C" void kernel_launch(void* const* d_in, const int* in_sizes, int n_in,
                              void* d_out, int out_size)
{
    const float* x      = (const float*)d_in[0];
    const float* params = (const float*)d_in[1];
    const float* W_ih   = (const float*)d_in[2];
    const float* W_hh   = (const float*)d_in[3];
    const float* b_ih   = (const float*)d_in[4];
    const float* b_hh   = (const float*)d_in[5];
    const float* W_lin  = (const float*)d_in[6];
    const float* b_lin  = (const float*)d_in[7];
    float* out = (float*)d_out;

    const int B = in_sizes[0] / TT;                 // 1024
    lstm_fused_kernel<<<B, 64>>>(x, params, W_ih, W_hh, b_ih, b_hh,
                                 W_lin, b_lin, out);
}

// round 9
// speedup vs baseline: 1.0215x; 1.0215x over previous
#include <cuda_runtime.h>
#include <cuda_fp16.h>
#include <cstdint>

#define TT 1024
#define HH 50
#define PP 16
#define RH 72   // ring row stride in halfs

__device__ __forceinline__ float tanh_hw(float v) {
    float r; asm("tanh.approx.f32 %0, %1;" : "=f"(r) : "f"(v)); return r;
}
__device__ __forceinline__ __half2 as_h2(unsigned u) {
    return *reinterpret_cast<const __half2*>(&u);
}
// named barrier over one batch's 2 warps (64 threads)
__device__ __forceinline__ void bar_pair(int id) {
    asm volatile("bar.sync %0, %1;" :: "r"(id), "r"(64) : "memory");
}

__global__ __launch_bounds__(128, 4)
void lstm_fused_kernel(const float* __restrict__ x,
                       const float* __restrict__ params,
                       const float* __restrict__ W_ih,
                       const float* __restrict__ W_hh,
                       const float* __restrict__ b_ih,
                       const float* __restrict__ b_hh,
                       const float* __restrict__ W_lin,
                       const float* __restrict__ b_lin,
                       float* __restrict__ out)
{
    __shared__ __align__(16) float  xs[2][TT];        // both batches' input rows
    __shared__ __align__(16) __half ring[2][32][RH];  // per-batch fp16 h ring
    __shared__ __align__(16) float  wlin[68];

    const int tid  = threadIdx.x;                     // 0..127
    const int pair = tid >> 6;                        // batch within CTA (0/1)
    const int u    = tid & 63;                        // unit index 0..63 (>=50 pads)
    const int jj   = min(u, HH - 1);
    const int b    = blockIdx.x * 2 + pair;           // global batch
    const int barid = pair + 1;                       // named barrier id (0 reserved)

    // ---- init: stage both x rows, wlin, zero h[-1] ----
    {
        #pragma unroll
        for (int i = tid; i < 512; i += 128) {        // 2 rows x 256 float4
            const int row = i >> 8, idx = i & 255;
            const float4* xr = reinterpret_cast<const float4*>(
                x + (size_t)(blockIdx.x * 2 + row) * TT);
            reinterpret_cast<float4*>(xs[row])[idx] = xr[idx];
        }
        if (u < HH) ring[pair][31][u] = __float2half_rn(0.0f);
        if (tid < 68) wlin[tid] = (tid < HH + PP) ? W_lin[tid] : 0.0f;
    }
    const float blin = b_lin[0];

    // ---- per-thread: all 4 gate rows (i,f,g,o) for unit jj ----
    __half2 w[4][25];
    float wih[4], bias[4];
    #pragma unroll
    for (int k = 0; k < 4; ++k) {
        const int r = k * HH + jj;
        wih[k]  = W_ih[r];
        bias[k] = b_ih[r] + b_hh[r];
        const float2* wr = reinterpret_cast<const float2*>(W_hh + r * HH);
        #pragma unroll
        for (int q = 0; q < 25; ++q) { float2 v = wr[q]; w[k][q] = __floats2half2_rn(v.x, v.y); }
    }
    __syncthreads();                                  // init done (all 128)

    float c = 0.0f;

    #pragma unroll 1
    for (int t = 0; t < TT; ++t) {
        const int cur  = t & 31;
        const int prev = (t + 31) & 31;

        // h[t-1]: 6 LDS.128 + 1 LDS.32, full-broadcast within the pair
        uint4 hv[6];
        const uint4* rp = reinterpret_cast<const uint4*>(&ring[pair][prev][0]);
        #pragma unroll
        for (int q = 0; q < 6; ++q) hv[q] = rp[q];
        const unsigned htail = reinterpret_cast<const unsigned*>(&ring[pair][prev][0])[24];
        const float xv = xs[pair][t];

        float raw[4];
        #pragma unroll
        for (int k = 0; k < 4; ++k) {
            __half2 a0 = __floats2half2_rn(0.f, 0.f), a1 = a0;
            #pragma unroll
            for (int q = 0; q < 6; ++q) {
                a0 = __hfma2(w[k][4 * q + 0], as_h2(hv[q].x), a0);
                a1 = __hfma2(w[k][4 * q + 1], as_h2(hv[q].y), a1);
                a0 = __hfma2(w[k][4 * q + 2], as_h2(hv[q].z), a0);
                a1 = __hfma2(w[k][4 * q + 3], as_h2(hv[q].w), a1);
            }
            a0 = __hfma2(w[k][24], as_h2(htail), a0);
            const __half2 s = __hadd2(a0, a1);
            raw[k] = fmaf(xv, wih[k], bias[k]) + __low2float(s) + __high2float(s);
        }

        const float vi = fmaf(0.5f, tanh_hw(0.5f * raw[0]), 0.5f);
        const float vf = fmaf(0.5f, tanh_hw(0.5f * raw[1]), 0.5f);
        const float vg = tanh_hw(raw[2]);
        const float vo = fmaf(0.5f, tanh_hw(0.5f * raw[3]), 0.5f);

        c = fmaf(vf, c, vi * vg);
        const float h = vo * tanh_hw(c);
        if (u < HH) ring[pair][cur][u] = __float2half_rn(h);

        bar_pair(barid);                              // h[cur] visible within the pair

        // ---- bulk output flush every 32 steps: first warp of the pair ----
        if ((t & 31) == 31) {
            if ((tid & 32) == 0) {
                const int lane = tid & 31;
                const int tg = t - 31 + lane;
                const __half* hr = ring[pair][lane];
                float s = blin;
                #pragma unroll
                for (int q = 0; q < 6; ++q) {
                    uint4 v = reinterpret_cast<const uint4*>(hr)[q];
                    float2 f0 = __half22float2(as_h2(v.x));
                    float2 f1 = __half22float2(as_h2(v.y));
                    float2 f2 = __half22float2(as_h2(v.z));
                    float2 f3 = __half22float2(as_h2(v.w));
                    s = fmaf(f0.x, wlin[8 * q + 0], s); s = fmaf(f0.y, wlin[8 * q + 1], s);
                    s = fmaf(f1.x, wlin[8 * q + 2], s); s = fmaf(f1.y, wlin[8 * q + 3], s);
                    s = fmaf(f2.x, wlin[8 * q + 4], s); s = fmaf(f2.y, wlin[8 * q + 5], s);
                    s = fmaf(f3.x, wlin[8 * q + 6], s); s = fmaf(f3.y, wlin[8 * q + 7], s);
                }
                {
                    float2 ft = __half22float2(as_h2(reinterpret_cast<const unsigned*>(hr)[24]));
                    s = fmaf(ft.x, wlin[48], s); s = fmaf(ft.y, wlin[49], s);
                }
                const float4* p4 = reinterpret_cast<const float4*>(
                    params + ((size_t)b * TT + tg) * PP);
                #pragma unroll
                for (int q = 0; q < 4; ++q) {
                    float4 p = __ldg(p4 + q);
                    s = fmaf(p.x, wlin[HH + 4 * q + 0], s);
                    s = fmaf(p.y, wlin[HH + 4 * q + 1], s);
                    s = fmaf(p.z, wlin[HH + 4 * q + 2], s);
                    s = fmaf(p.w, wlin[HH + 4 * q + 3], s);
                }
                out[(size_t)b * TT + tg] = s;
            }
            bar_pair(barid);                          // flush reads done before slot reuse
        }
    }
}

extern "C" void kernel_launch(void* const* d_in, const int* in_sizes, int n_in,
                              void* d_out, int out_size)
{
    const float* x      = (const float*)d_in[0];
    const float* params = (const float*)d_in[1];
    const float* W_ih   = (const float*)d_in[2];
    const float* W_hh   = (const float*)d_in[3];
    const float* b_ih   = (const float*)d_in[4];
    const float* b_hh   = (const float*)d_in[5];
    const float* W_lin  = (const float*)d_in[6];
    const float* b_lin  = (const float*)d_in[7];
    float* out = (float*)d_out;

    const int B = in_sizes[0] / TT;                   // 1024
    lstm_fused_kernel<<<B / 2, 128>>>(x, params, W_ih, W_hh, b_ih, b_hh,
                                      W_lin, b_lin, out);
}